// round 2
// baseline (speedup 1.0000x reference)
#include <cuda_runtime.h>
#include <math.h>

#define NN 512
#define MM 2048
#define FEAT 1024
#define GG 16
#define DG 64

// ---------------- scratch (device globals; no allocation) ----------------
__device__ float d_q[NN * FEAT];                    // (q + u) / 8, [n][g*64+d]
__device__ float d_k[MM * FEAT];                    // k, [m][g*64+d]
__device__ float d_v[MM * FEAT];                    // V = ref_feat @ Wv_flat^T, [m][g*64+d]
__device__ float d_logw[(size_t)GG * NN * MM];      // log(relu(Wg.pe)+1e-6), [g][n][m]
__device__ float4 d_roip[NN];                       // cx, cy, w, h
__device__ float4 d_refp[MM];

// ---------------- box param prep ----------------
__global__ void prep_boxes_kernel(const float* __restrict__ bbox,
                                  const float* __restrict__ refb)
{
    int i = blockIdx.x * 256 + threadIdx.x;
    if (i < NN) {
        float x0 = bbox[i*4+0], y0 = bbox[i*4+1], x1 = bbox[i*4+2], y1 = bbox[i*4+3];
        d_roip[i] = make_float4(0.5f*(x0+x1), 0.5f*(y0+y1), x1 - x0 + 1.0f, y1 - y0 + 1.0f);
    }
    if (i < MM) {
        float x0 = refb[i*4+0], y0 = refb[i*4+1], x1 = refb[i*4+2], y1 = refb[i*4+3];
        d_refp[i] = make_float4(0.5f*(x0+x1), 0.5f*(y0+y1), x1 - x0 + 1.0f, y1 - y0 + 1.0f);
    }
}

// ---------------- position-embedding prior:  logw[g][n][m] ----------------
__global__ __launch_bounds__(128)
void logw_kernel(const float* __restrict__ Wg_w, const float* __restrict__ Wg_b)
{
    __shared__ float wg[GG * 64];
    __shared__ float wgb[GG];
    int n = blockIdx.y;
    int m = blockIdx.x * 128 + threadIdx.x;
    for (int t = threadIdx.x; t < GG * 64; t += 128) wg[t] = Wg_w[t];
    if (threadIdx.x < GG) wgb[threadIdx.x] = Wg_b[threadIdx.x];
    float4 rp = d_roip[n];
    float4 fp = d_refp[m];
    __syncthreads();

    float pos[4];
    pos[0] = logf(fabsf((rp.x - fp.x) / rp.z) + 1e-3f);
    pos[1] = logf(fabsf((rp.y - fp.y) / rp.w) + 1e-3f);
    pos[2] = logf(rp.z / fp.z);
    pos[3] = logf(rp.w / fp.w);

    // dim_mat = 1000^(f/8), f=0..7 (correctly rounded fp32)
    const float dm[8] = {1.0f, 2.3713737f, 5.6234131f, 13.335214f,
                         31.622776f, 74.989420f, 177.82794f, 421.69650f};
    float emb[64];
#pragma unroll
    for (int i = 0; i < 4; i++) {
        float p100 = pos[i] * 100.0f;
#pragma unroll
        for (int f = 0; f < 8; f++) {
            float x = p100 / dm[f];
            float s, c;
            sincosf(x, &s, &c);
            emb[i*16 + f]     = s;
            emb[i*16 + 8 + f] = c;
        }
    }
    size_t base = (size_t)n * MM + m;
#pragma unroll 1
    for (int g = 0; g < GG; g++) {
        float a = wgb[g];
#pragma unroll
        for (int e = 0; e < 64; e++) a += wg[g*64 + e] * emb[e];
        a = fmaxf(a, 0.0f) + 1e-6f;
        d_logw[(size_t)g * NN * MM + base] = logf(a);
    }
}

// ---------------- generic NT SGEMM: C[r][o] = (A[r,:].B[o,:] + bias + bias2)*scale ----
__global__ __launch_bounds__(256)
void sgemm_nt_kernel(const float* __restrict__ A, const float* __restrict__ B,
                     const float* __restrict__ bias, const float* __restrict__ bias2,
                     float scale, float* __restrict__ C, int R, int O, int K)
{
    __shared__ float As[8][128];
    __shared__ float Bs[8][128];
    int br = blockIdx.y * 128;
    int bo = blockIdx.x * 128;
    int tid = threadIdx.x;
    int lr = tid >> 1;
    int lc = (tid & 1) * 4;
    int tx = tid & 15;
    int ty = tid >> 4;
    const float* Ap = A + (size_t)(br + lr) * K + lc;
    const float* Bp = B + (size_t)(bo + lr) * K + lc;

    float acc[8][8];
#pragma unroll
    for (int i = 0; i < 8; i++)
#pragma unroll
        for (int j = 0; j < 8; j++) acc[i][j] = 0.0f;

    for (int k0 = 0; k0 < K; k0 += 8) {
        float4 a4 = *(const float4*)(Ap + k0);
        float4 b4 = *(const float4*)(Bp + k0);
        As[lc+0][lr] = a4.x; As[lc+1][lr] = a4.y; As[lc+2][lr] = a4.z; As[lc+3][lr] = a4.w;
        Bs[lc+0][lr] = b4.x; Bs[lc+1][lr] = b4.y; Bs[lc+2][lr] = b4.z; Bs[lc+3][lr] = b4.w;
        __syncthreads();
#pragma unroll
        for (int kk = 0; kk < 8; kk++) {
            float ra[8], rb[8];
            *(float4*)&ra[0] = *(const float4*)&As[kk][ty*8];
            *(float4*)&ra[4] = *(const float4*)&As[kk][ty*8 + 4];
            *(float4*)&rb[0] = *(const float4*)&Bs[kk][tx*8];
            *(float4*)&rb[4] = *(const float4*)&Bs[kk][tx*8 + 4];
#pragma unroll
            for (int i = 0; i < 8; i++)
#pragma unroll
                for (int j = 0; j < 8; j++) acc[i][j] += ra[i] * rb[j];
        }
        __syncthreads();
    }
#pragma unroll
    for (int i = 0; i < 8; i++) {
        int r = br + ty*8 + i;
#pragma unroll
        for (int j = 0; j < 8; j++) {
            int o = bo + tx*8 + j;
            float v = acc[i][j];
            if (bias)  v += bias[o];
            if (bias2) v += bias2[o];
            C[(size_t)r * O + o] = v * scale;
        }
    }
}

// ---------------- fused flash attention + V contraction ----------------
// grid (NN/64, GG), 256 threads, 64-wide m tiles. Dynamic smem = 4*64*64 floats.
__global__ __launch_bounds__(256)
void attn_kernel(const float* __restrict__ Wv_b, float* __restrict__ out)
{
    extern __shared__ float sm[];
    float* Qs  = sm;            // [d][n]  (transposed)
    float* KVs = sm + 4096;     // K: [d][m] (transposed); later V: [m][d]
    float* Ls  = sm + 8192;     // logw tile [n][m]
    float* Ps  = sm + 12288;    // logits/probs [m][n]
    __shared__ float rmax[64], rsum[64], rfac[64];

    int g  = blockIdx.y;
    int n0 = blockIdx.x * 64;
    int tid = threadIdx.x;
    int tx = tid & 15, ty = tid >> 4;

    // load Q tile, transpose to [d][n]
    for (int idx = tid; idx < 64 * 16; idx += 256) {
        int n = idx >> 4, c4 = (idx & 15) * 4;
        float4 v = *(const float4*)&d_q[(size_t)(n0 + n) * FEAT + g*64 + c4];
        Qs[(c4+0)*64 + n] = v.x; Qs[(c4+1)*64 + n] = v.y;
        Qs[(c4+2)*64 + n] = v.z; Qs[(c4+3)*64 + n] = v.w;
    }
    if (tid < 64) { rmax[tid] = -1e30f; rsum[tid] = 0.0f; }

    float accO[4][4];
#pragma unroll
    for (int i = 0; i < 4; i++)
#pragma unroll
        for (int j = 0; j < 4; j++) accO[i][j] = 0.0f;
    __syncthreads();

    for (int m0 = 0; m0 < MM; m0 += 64) {
        // K tile transposed to [d][m]
        for (int idx = tid; idx < 64 * 16; idx += 256) {
            int mm = idx >> 4, c4 = (idx & 15) * 4;
            float4 v = *(const float4*)&d_k[(size_t)(m0 + mm) * FEAT + g*64 + c4];
            KVs[(c4+0)*64 + mm] = v.x; KVs[(c4+1)*64 + mm] = v.y;
            KVs[(c4+2)*64 + mm] = v.z; KVs[(c4+3)*64 + mm] = v.w;
        }
        // logw tile, straight copy [n][m]
        for (int idx = tid; idx < 64 * 16; idx += 256) {
            int n = idx >> 4, c4 = (idx & 15) * 4;
            *(float4*)&Ls[n*64 + c4] =
                *(const float4*)&d_logw[((size_t)g * NN + (n0 + n)) * MM + m0 + c4];
        }
        __syncthreads();

        // S = Qs^T Ks  (each thread 4x4)
        float s[4][4];
#pragma unroll
        for (int i = 0; i < 4; i++)
#pragma unroll
            for (int j = 0; j < 4; j++) s[i][j] = 0.0f;
#pragma unroll 16
        for (int d = 0; d < 64; d++) {
            float qr[4], kr[4];
            *(float4*)qr = *(const float4*)&Qs[d*64 + ty*4];
            *(float4*)kr = *(const float4*)&KVs[d*64 + tx*4];
#pragma unroll
            for (int i = 0; i < 4; i++)
#pragma unroll
                for (int j = 0; j < 4; j++) s[i][j] += qr[i] * kr[j];
        }
        // + logw, store logits transposed: Ps[m][n]
#pragma unroll
        for (int i = 0; i < 4; i++)
#pragma unroll
            for (int j = 0; j < 4; j++)
                Ps[(tx*4 + j)*64 + (ty*4 + i)] = s[i][j] + Ls[(ty*4 + i)*64 + tx*4 + j];
        __syncthreads();

        // online softmax (threads 0..63, one row each) ...
        if (tid < 64) {
            float om = rmax[tid];
            float nm = om;
#pragma unroll 8
            for (int mv = 0; mv < 64; mv++) nm = fmaxf(nm, Ps[mv*64 + tid]);
            float fac = __expf(om - nm);
            float sum = 0.0f;
#pragma unroll 8
            for (int mv = 0; mv < 64; mv++) {
                float p = __expf(Ps[mv*64 + tid] - nm);
                Ps[mv*64 + tid] = p;
                sum += p;
            }
            rmax[tid] = nm;
            rsum[tid] = rsum[tid] * fac + sum;
            rfac[tid] = fac;
        }
        // ... while all threads stream V into the (now free) K buffer, natural [m][d]
        for (int idx = tid; idx < 64 * 16; idx += 256) {
            int mm = idx >> 4, c4 = (idx & 15) * 4;
            *(float4*)&KVs[mm*64 + c4] =
                *(const float4*)&d_v[(size_t)(m0 + mm) * FEAT + g*64 + c4];
        }
        __syncthreads();

        // rescale accumulators, then O += P^T V
        float fi[4];
#pragma unroll
        for (int i = 0; i < 4; i++) fi[i] = rfac[ty*4 + i];
#pragma unroll
        for (int i = 0; i < 4; i++)
#pragma unroll
            for (int j = 0; j < 4; j++) accO[i][j] *= fi[i];
#pragma unroll 16
        for (int mm = 0; mm < 64; mm++) {
            float pr[4], vr[4];
            *(float4*)pr = *(const float4*)&Ps[mm*64 + ty*4];
            *(float4*)vr = *(const float4*)&KVs[mm*64 + tx*4];
#pragma unroll
            for (int i = 0; i < 4; i++)
#pragma unroll
                for (int j = 0; j < 4; j++) accO[i][j] += pr[i] * vr[j];
        }
        __syncthreads();
    }

    // epilogue: divide by softmax denominator, add Wv_b, write out
#pragma unroll
    for (int i = 0; i < 4; i++) {
        int n = n0 + ty*4 + i;
        float inv = 1.0f / rsum[ty*4 + i];
#pragma unroll
        for (int j = 0; j < 4; j++) {
            int o = g*64 + tx*4 + j;
            out[(size_t)n * FEAT + o] = accO[i][j] * inv + Wv_b[o];
        }
    }
}

// ---------------- launch ----------------
extern "C" void kernel_launch(void* const* d_in, const int* in_sizes, int n_in,
                              void* d_out, int out_size)
{
    const float* bbox     = (const float*)d_in[0];
    const float* ref_bbox = (const float*)d_in[1];
    const float* roi_feat = (const float*)d_in[2];
    const float* ref_feat = (const float*)d_in[3];
    const float* Wg_w     = (const float*)d_in[4];
    const float* Wg_b     = (const float*)d_in[5];
    const float* Wq_w     = (const float*)d_in[6];
    const float* Wq_b     = (const float*)d_in[7];
    const float* Wk_w     = (const float*)d_in[8];
    const float* Wk_b     = (const float*)d_in[9];
    const float* Wv_w     = (const float*)d_in[10];   // [G,DG,FEAT] == flat [1024,1024]
    const float* Wv_b     = (const float*)d_in[11];
    const float* u        = (const float*)d_in[12];   // [G,1,64] == flat [1024]
    float* out = (float*)d_out;

    (void)in_sizes; (void)n_in; (void)out_size;

    cudaFuncSetAttribute(attn_kernel, cudaFuncAttributeMaxDynamicSharedMemorySize, 65536);

    float *qp, *kp, *vp;
    cudaGetSymbolAddress((void**)&qp, d_q);
    cudaGetSymbolAddress((void**)&kp, d_k);
    cudaGetSymbolAddress((void**)&vp, d_v);

    prep_boxes_kernel<<<8, 256>>>(bbox, ref_bbox);
    logw_kernel<<<dim3(MM / 128, NN), 128>>>(Wg_w, Wg_b);

    // q = (roi @ Wq^T + Wq_b + u) * 0.125   (folds content bias u and 1/sqrt(64))
    sgemm_nt_kernel<<<dim3(FEAT/128, NN/128), 256>>>(roi_feat, Wq_w, Wq_b, u, 0.125f,
                                                     qp, NN, FEAT, FEAT);
    // k = ref @ Wk^T + Wk_b
    sgemm_nt_kernel<<<dim3(FEAT/128, MM/128), 256>>>(ref_feat, Wk_w, Wk_b, nullptr, 1.0f,
                                                     kp, MM, FEAT, FEAT);
    // V = ref @ Wv_flat^T   (Wv_b added in attention epilogue)
    sgemm_nt_kernel<<<dim3(FEAT/128, MM/128), 256>>>(ref_feat, Wv_w, nullptr, nullptr, 1.0f,
                                                     vp, MM, FEAT, FEAT);

    attn_kernel<<<dim3(NN/64, GG), 256, 65536>>>(Wv_b, out);
}